// round 1
// baseline (speedup 1.0000x reference)
#include <cuda_runtime.h>
#include <math.h>

// ---------------- problem constants ----------------
#define BATCH 4
#define CIN   64
#define CMOD  128          // d_model
#define HW    64           // output spatial side
#define L     4096         // HW*HW
#define M_TOT (BATCH*L)    // 16384 token rows
#define DIN   256          // d_inner
#define DST   16           // d_state
#define DTR   8            // dt_rank
#define XPROJ_E 40         // dt_rank + 2*d_state

// ---------------- scratch (device globals; no allocs allowed) ----------------
__device__ float g_y   [BATCH * CMOD * L];   // gelu(bn(conv)) in [b][c][l] layout (residual + GEMM1 A)
__device__ float g_xz  [M_TOT * 2 * DIN];    // in-proj output [m][512]
__device__ float g_xin [M_TOT * DIN];        // after conv1d+silu [m][256]
__device__ float g_xdbl[M_TOT * XPROJ_E];    // [m][40] : dt(8) | B(16) | C(16)
__device__ float g_yg  [M_TOT * DIN];        // gated scan output [m][256]

// ---------------- helpers ----------------
__device__ __forceinline__ float silu_f(float v){ return v / (1.f + __expf(-v)); }
__device__ __forceinline__ float softplus_f(float v){ return (v > 20.f) ? v : log1pf(__expf(v)); }
__device__ __forceinline__ float gelu_f(float v){ return 0.5f * v * (1.f + erff(v * 0.70710678118654752f)); }

// =====================================================================
// K1: conv3x3 stride2 pad1 (64->128ch) + bias + BN(eval) + exact GELU
// block: 256 threads; spatial tile 32x32 (2x2 per thread); 8 oc per block
// grid: (4 spatial tiles, 16 oc groups, 4 batch)
// =====================================================================
__global__ void k_conv(const float* __restrict__ x, const float* __restrict__ w,
                       const float* __restrict__ cb, const float* __restrict__ bng,
                       const float* __restrict__ bnb, const float* __restrict__ bnm,
                       const float* __restrict__ bnv)
{
    __shared__ float in_s[2 * 65 * 65];   // 2 input channels x 65x65 halo tile
    __shared__ float w_s[2 * 9 * 8];      // [ci*9+k][oc]

    const int t  = threadIdx.x;
    const int tx = t & 15, ty = t >> 4;
    const int bx = blockIdx.x;
    const int oh0 = (bx >> 1) * 32, ow0 = (bx & 1) * 32;
    const int oc0 = blockIdx.y * 8;
    const int b   = blockIdx.z;
    const int ih0 = oh0 * 2 - 1, iw0 = ow0 * 2 - 1;

    float acc[2][2][8];
    #pragma unroll
    for (int a = 0; a < 2; a++)
        #pragma unroll
        for (int q = 0; q < 2; q++)
            #pragma unroll
            for (int oc = 0; oc < 8; oc++) acc[a][q][oc] = 0.f;

    for (int cc = 0; cc < CIN; cc += 2) {
        __syncthreads();
        // load 2 x 65 x 65 input tile (zero padded)
        for (int idx = t; idx < 2 * 65 * 65; idx += 256) {
            int ci = idx / 4225, rem = idx - ci * 4225;
            int r = rem / 65, cl = rem - r * 65;
            int ih = ih0 + r, iw = iw0 + cl;
            float v = 0.f;
            if (ih >= 0 && ih < 128 && iw >= 0 && iw < 128)
                v = x[((b * CIN + cc + ci) * 128 + ih) * 128 + iw];
            in_s[idx] = v;
        }
        // load 8 oc x 2 ci x 9 weights
        if (t < 144) {
            int oc = t & 7, rk = t >> 3;      // rk = ci*9 + k
            int ci = rk / 9, k = rk - ci * 9;
            w_s[t] = w[(oc0 + oc) * (CIN * 9) + (cc + ci) * 9 + k];
        }
        __syncthreads();

        #pragma unroll
        for (int ci = 0; ci < 2; ci++)
            #pragma unroll
            for (int kh = 0; kh < 3; kh++)
                #pragma unroll
                for (int kw = 0; kw < 3; kw++) {
                    float wr[8];
                    #pragma unroll
                    for (int oc = 0; oc < 8; oc++) wr[oc] = w_s[(ci * 9 + kh * 3 + kw) * 8 + oc];
                    #pragma unroll
                    for (int a = 0; a < 2; a++) {
                        int r = 2 * (ty + a * 16) + kh;
                        #pragma unroll
                        for (int q = 0; q < 2; q++) {
                            int cl = 2 * (tx + q * 16) + kw;
                            float iv = in_s[ci * 4225 + r * 65 + cl];
                            #pragma unroll
                            for (int oc = 0; oc < 8; oc++)
                                acc[a][q][oc] = fmaf(iv, wr[oc], acc[a][q][oc]);
                        }
                    }
                }
    }

    // epilogue: bias + BN + GELU, write [b][c][l]
    #pragma unroll
    for (int oc = 0; oc < 8; oc++) {
        int c = oc0 + oc;
        float inv = bng[c] * rsqrtf(bnv[c] + 1e-5f);
        float mu = bnm[c], bb = bnb[c], bi = cb[c];
        #pragma unroll
        for (int a = 0; a < 2; a++) {
            int oh = oh0 + ty + a * 16;
            #pragma unroll
            for (int q = 0; q < 2; q++) {
                int ow = ow0 + tx + q * 16;
                float v = acc[a][q][oc] + bi;
                v = (v - mu) * inv + bb;
                g_y[(b * CMOD + c) * L + oh * HW + ow] = gelu_f(v);
            }
        }
    }
}

// =====================================================================
// K2: in-proj GEMM  xz[m][e] = sum_k y[b][k][l] * in_w[e][k]
// BM=128 (m), BE=128 (e), BK=8 ; 256 threads, 8x8 microtile
// grid: (4 e-tiles, 128 m-tiles)
// =====================================================================
__global__ void k_gemm_xz(const float* __restrict__ in_w)
{
    __shared__ float As[8][128];   // [k][m]
    __shared__ float Bs[8][128];   // [k][e]
    const int t  = threadIdx.x;
    const int tx = t & 15, ty = t >> 4;
    const int e0 = blockIdx.x * 128;
    const int m0 = blockIdx.y * 128;
    const int b  = m0 >> 12;          // 4096 per batch, BM divides it
    const int l0 = m0 & 4095;

    float acc[8][8];
    #pragma unroll
    for (int i = 0; i < 8; i++)
        #pragma unroll
        for (int j = 0; j < 8; j++) acc[i][j] = 0.f;

    for (int k0 = 0; k0 < CMOD; k0 += 8) {
        __syncthreads();
        {
            // A tile: read g_y[(b*128 + k)*4096 + l0 + m] coalesced along l
            int row4 = (t & 31) * 4;          // m within tile
            int k    = t >> 5;                // 0..7
            float4 av = *(const float4*)&g_y[(b * CMOD + k0 + k) * L + l0 + row4];
            *(float4*)&As[k][row4] = av;
            // B tile: in_w rows (K-contiguous)
            int row = t >> 1, kq = (t & 1) * 4;
            float4 bv = *(const float4*)&in_w[(e0 + row) * CMOD + k0 + kq];
            Bs[kq + 0][row] = bv.x; Bs[kq + 1][row] = bv.y;
            Bs[kq + 2][row] = bv.z; Bs[kq + 3][row] = bv.w;
        }
        __syncthreads();
        #pragma unroll
        for (int k = 0; k < 8; k++) {
            float a[8], bb[8];
            *(float4*)&a[0] = *(float4*)&As[k][ty * 4];
            *(float4*)&a[4] = *(float4*)&As[k][ty * 4 + 64];
            *(float4*)&bb[0] = *(float4*)&Bs[k][tx * 4];
            *(float4*)&bb[4] = *(float4*)&Bs[k][tx * 4 + 64];
            #pragma unroll
            for (int i = 0; i < 8; i++)
                #pragma unroll
                for (int j = 0; j < 8; j++)
                    acc[i][j] = fmaf(a[i], bb[j], acc[i][j]);
        }
    }
    #pragma unroll
    for (int i = 0; i < 8; i++) {
        int m = m0 + ty * 4 + (i & 3) + (i >> 2) * 64;
        float4 v0 = make_float4(acc[i][0], acc[i][1], acc[i][2], acc[i][3]);
        float4 v1 = make_float4(acc[i][4], acc[i][5], acc[i][6], acc[i][7]);
        *(float4*)&g_xz[(size_t)m * 512 + e0 + tx * 4] = v0;
        *(float4*)&g_xz[(size_t)m * 512 + e0 + tx * 4 + 64] = v1;
    }
}

// =====================================================================
// K3: depthwise causal conv1d (k=4, left pad 3) + bias + SiLU
// block: 256 threads (=d), grid (32 l-chunks, 4 b)
// =====================================================================
__global__ void k_conv1d(const float* __restrict__ w, const float* __restrict__ bias)
{
    const int d  = threadIdx.x;
    const int b  = blockIdx.y;
    const int l0 = blockIdx.x * 128;
    const float w0 = w[d * 4 + 0], w1 = w[d * 4 + 1], w2 = w[d * 4 + 2], w3 = w[d * 4 + 3];
    const float bs = bias[d];

    float xm3 = (l0 - 3 >= 0) ? g_xz[(size_t)(b * L + l0 - 3) * 512 + d] : 0.f;
    float xm2 = (l0 - 2 >= 0) ? g_xz[(size_t)(b * L + l0 - 2) * 512 + d] : 0.f;
    float xm1 = (l0 - 1 >= 0) ? g_xz[(size_t)(b * L + l0 - 1) * 512 + d] : 0.f;

    for (int l = l0; l < l0 + 128; l++) {
        float xc = g_xz[(size_t)(b * L + l) * 512 + d];
        float v = fmaf(w0, xm3, fmaf(w1, xm2, fmaf(w2, xm1, fmaf(w3, xc, bs))));
        g_xin[(size_t)(b * L + l) * DIN + d] = silu_f(v);
        xm3 = xm2; xm2 = xm1; xm1 = xc;
    }
}

// =====================================================================
// K4: x-proj GEMM  x_dbl[m][e<40] = sum_k x_in[m][k] * xproj_w[e][k]
// block (40,4)=160 threads; BM=16 (4 m rows per thread); K=256 fully in smem
// =====================================================================
__global__ void k_xproj(const float* __restrict__ xpw)
{
    __shared__ float xin_s[16 * 256];
    const int m0 = blockIdx.x * 16;
    const int t = threadIdx.y * 40 + threadIdx.x;
    const float4* src = (const float4*)&g_xin[(size_t)m0 * 256];
    for (int idx = t; idx < 16 * 256 / 4; idx += 160)
        ((float4*)xin_s)[idx] = src[idx];
    __syncthreads();

    const int e = threadIdx.x, ty = threadIdx.y;
    float acc[4] = {0.f, 0.f, 0.f, 0.f};
    const float4* wp = (const float4*)&xpw[e * 256];
    #pragma unroll 4
    for (int k4 = 0; k4 < 64; k4++) {
        float4 wv = __ldg(&wp[k4]);
        #pragma unroll
        for (int i = 0; i < 4; i++) {
            float4 a = ((const float4*)xin_s)[(ty * 4 + i) * 64 + k4];
            acc[i] += a.x * wv.x + a.y * wv.y + a.z * wv.z + a.w * wv.w;
        }
    }
    #pragma unroll
    for (int i = 0; i < 4; i++)
        g_xdbl[(size_t)(m0 + ty * 4 + i) * XPROJ_E + e] = acc[i];
}

// =====================================================================
// K5: fused delta (softplus(dt @ Wdt^T + b)) + selective scan + gate
// block: 128 threads = 8 d x 16 n ; grid (32 d-groups, 4 b)
// chunked over L with CH=64 smem staging
// =====================================================================
__global__ void k_scan(const float* __restrict__ A_log, const float* __restrict__ dtw_g,
                       const float* __restrict__ dtb_g, const float* __restrict__ Dp_g)
{
    __shared__ float dt_s [64 * 8];
    __shared__ float B_s  [64 * 16];
    __shared__ float C_s  [64 * 16];
    __shared__ float xin_s[64 * 8];
    __shared__ float del_s[64 * 8];
    __shared__ float ys_s [64 * 8];

    const int b  = blockIdx.y;
    const int d0 = blockIdx.x * 8;
    const int t  = threadIdx.x;
    const int n  = t & 15, dl = t >> 4;          // scan mapping
    const int d  = d0 + dl;
    const float A_dn = -__expf(A_log[d * DST + n]);

    const int dcol = t & 7;                      // delta / flush mapping
    const int lrow = t >> 3;
    float dtw[8];
    #pragma unroll
    for (int r = 0; r < 8; r++) dtw[r] = dtw_g[(d0 + dcol) * DTR + r];
    const float dtb = dtb_g[d0 + dcol];
    const float Dpv = Dp_g[d0 + dcol];

    float h = 0.f;
    for (int c = 0; c < 64; c++) {
        const int mb = b * L + c * 64;
        __syncthreads();
        // stage tiles
        #pragma unroll
        for (int j = 0; j < 4; j++) {
            int idx = t + j * 128; int l = idx >> 3, r = idx & 7;
            dt_s[idx] = g_xdbl[(size_t)(mb + l) * XPROJ_E + r];
        }
        #pragma unroll
        for (int j = 0; j < 8; j++) {
            int idx = t + j * 128; int l = idx >> 4, nn = idx & 15;
            B_s[idx] = g_xdbl[(size_t)(mb + l) * XPROJ_E + 8 + nn];
            C_s[idx] = g_xdbl[(size_t)(mb + l) * XPROJ_E + 24 + nn];
        }
        #pragma unroll
        for (int j = 0; j < 4; j++) {
            int idx = t + j * 128; int l = idx >> 3, dd = idx & 7;
            xin_s[idx] = g_xin[(size_t)(mb + l) * DIN + d0 + dd];
        }
        __syncthreads();
        // delta = softplus(dt . dtw + dtb)
        #pragma unroll
        for (int j = 0; j < 4; j++) {
            int l = lrow + j * 16;
            float v = dtb;
            #pragma unroll
            for (int r = 0; r < 8; r++) v = fmaf(dt_s[l * 8 + r], dtw[r], v);
            del_s[l * 8 + dcol] = softplus_f(v);
        }
        __syncthreads();
        // sequential scan over the chunk
        #pragma unroll 4
        for (int l = 0; l < 64; l++) {
            float dlt = del_s[l * 8 + dl];
            float xv  = xin_s[l * 8 + dl];
            float dA  = __expf(dlt * A_dn);
            float dBu = dlt * B_s[l * 16 + n] * xv;
            h = fmaf(dA, h, dBu);
            float p = h * C_s[l * 16 + n];
            p += __shfl_xor_sync(0xffffffffu, p, 8);
            p += __shfl_xor_sync(0xffffffffu, p, 4);
            p += __shfl_xor_sync(0xffffffffu, p, 2);
            p += __shfl_xor_sync(0xffffffffu, p, 1);
            if (n == 0) ys_s[l * 8 + dl] = p;
        }
        __syncthreads();
        // gate + flush: yg = (ys + xin*Dp) * silu(z)
        #pragma unroll
        for (int j = 0; j < 4; j++) {
            int idx = t + j * 128; int l = idx >> 3, dd = idx & 7;
            float z = g_xz[(size_t)(mb + l) * 512 + 256 + d0 + dd];
            float yv = fmaf(xin_s[idx], Dpv, ys_s[idx]) * silu_f(z);
            g_yg[(size_t)(mb + l) * DIN + d0 + dd] = yv;
        }
    }
}

// =====================================================================
// K6: out-proj GEMM + residual:
// out[b][c][l] = y[b][c][l] + sum_d yg[m][d] * out_w[c][d]
// BM=128 (m = fast write dim), BC=128 (all c), BK=8; 256 threads
// grid: 128 m-tiles
// =====================================================================
__global__ void k_gemm_out(const float* __restrict__ ow, float* __restrict__ out)
{
    __shared__ float As[8][128];   // [k][m] from g_yg
    __shared__ float Bs[8][128];   // [k][c] from out_w
    const int t  = threadIdx.x;
    const int tx = t & 15, ty = t >> 4;
    const int m0 = blockIdx.x * 128;
    const int b  = m0 >> 12;
    const int l0 = m0 & 4095;

    float acc[8][8];
    #pragma unroll
    for (int i = 0; i < 8; i++)
        #pragma unroll
        for (int j = 0; j < 8; j++) acc[i][j] = 0.f;

    for (int k0 = 0; k0 < DIN; k0 += 8) {
        __syncthreads();
        {
            int row = t >> 1, kq = (t & 1) * 4;
            float4 av = *(const float4*)&g_yg[(size_t)(m0 + row) * DIN + k0 + kq];
            As[kq + 0][row] = av.x; As[kq + 1][row] = av.y;
            As[kq + 2][row] = av.z; As[kq + 3][row] = av.w;
            float4 bv = *(const float4*)&ow[row * DIN + k0 + kq];
            Bs[kq + 0][row] = bv.x; Bs[kq + 1][row] = bv.y;
            Bs[kq + 2][row] = bv.z; Bs[kq + 3][row] = bv.w;
        }
        __syncthreads();
        #pragma unroll
        for (int k = 0; k < 8; k++) {
            float am[8], bc[8];
            *(float4*)&am[0] = *(float4*)&As[k][tx * 4];
            *(float4*)&am[4] = *(float4*)&As[k][tx * 4 + 64];
            *(float4*)&bc[0] = *(float4*)&Bs[k][ty * 4];
            *(float4*)&bc[4] = *(float4*)&Bs[k][ty * 4 + 64];
            #pragma unroll
            for (int ci = 0; ci < 8; ci++)
                #pragma unroll
                for (int mj = 0; mj < 8; mj++)
                    acc[ci][mj] = fmaf(bc[ci], am[mj], acc[ci][mj]);
        }
    }
    #pragma unroll
    for (int ci = 0; ci < 8; ci++) {
        int c = ty * 4 + (ci & 3) + (ci >> 2) * 64;
        size_t base = (size_t)(b * CMOD + c) * L + l0;
        float4 r0 = *(const float4*)&g_y[base + tx * 4];
        r0.x += acc[ci][0]; r0.y += acc[ci][1]; r0.z += acc[ci][2]; r0.w += acc[ci][3];
        *(float4*)&out[base + tx * 4] = r0;
        float4 r1 = *(const float4*)&g_y[base + tx * 4 + 64];
        r1.x += acc[ci][4]; r1.y += acc[ci][5]; r1.z += acc[ci][6]; r1.w += acc[ci][7];
        *(float4*)&out[base + tx * 4 + 64] = r1;
    }
}

// =====================================================================
extern "C" void kernel_launch(void* const* d_in, const int* in_sizes, int n_in,
                              void* d_out, int out_size)
{
    const float* x        = (const float*)d_in[0];
    const float* conv_w   = (const float*)d_in[1];
    const float* conv_b   = (const float*)d_in[2];
    const float* bn_g     = (const float*)d_in[3];
    const float* bn_b     = (const float*)d_in[4];
    const float* bn_mean  = (const float*)d_in[5];
    const float* bn_var   = (const float*)d_in[6];
    const float* in_w     = (const float*)d_in[7];
    const float* conv1d_w = (const float*)d_in[8];
    const float* conv1d_b = (const float*)d_in[9];
    const float* xproj_w  = (const float*)d_in[10];
    const float* dtproj_w = (const float*)d_in[11];
    const float* dtproj_b = (const float*)d_in[12];
    const float* A_log    = (const float*)d_in[13];
    const float* Dp       = (const float*)d_in[14];
    const float* out_w    = (const float*)d_in[15];
    float* out = (float*)d_out;

    k_conv    <<<dim3(4, 16, 4), 256>>>(x, conv_w, conv_b, bn_g, bn_b, bn_mean, bn_var);
    k_gemm_xz <<<dim3(4, 128), 256>>>(in_w);
    k_conv1d  <<<dim3(32, 4), 256>>>(conv1d_w, conv1d_b);
    k_xproj   <<<1024, dim3(40, 4)>>>(xproj_w);
    k_scan    <<<dim3(32, 4), 128>>>(A_log, dtproj_w, dtproj_b, Dp);
    k_gemm_out<<<128, 256>>>(out_w, out);
}

// round 3
// speedup vs baseline: 1.6837x; 1.6837x over previous
#include <cuda_runtime.h>
#include <math.h>

// ---------------- problem constants ----------------
#define BATCH 4
#define CIN   64
#define CMOD  128          // d_model
#define HW    64           // output spatial side
#define L     4096         // HW*HW
#define M_TOT (BATCH*L)    // 16384 token rows
#define DIN   256          // d_inner
#define DST   16           // d_state
#define DTR   8            // dt_rank
#define XPROJ_E 40         // dt_rank + 2*d_state
#define NC    32           // scan chunks
#define LC    128          // chunk length (NC*LC == L)

// ---------------- scratch (device globals; no allocs allowed) ----------------
__device__ float g_y   [BATCH * CMOD * L];   // gelu(bn(conv)) in [b][c][l]
__device__ float g_xz  [M_TOT * 2 * DIN];    // in-proj output [m][512]
__device__ float g_xin [M_TOT * DIN];        // after conv1d+silu [m][256]
__device__ float g_xdbl[M_TOT * XPROJ_E];    // [m][40] : dt(8) | B(16) | C(16)
__device__ float g_yg  [M_TOT * DIN];        // gated scan output [m][256]
__device__ float g_q   [BATCH * DIN * DST * NC];  // chunk local final state
__device__ float g_ap  [BATCH * DIN * DST * NC];  // chunk decay aggregate
__device__ float g_hin [BATCH * DIN * DST * NC];  // state entering each chunk

// ---------------- helpers ----------------
__device__ __forceinline__ float silu_f(float v){ return v / (1.f + __expf(-v)); }
__device__ __forceinline__ float softplus_f(float v){ return (v > 20.f) ? v : log1pf(__expf(v)); }
__device__ __forceinline__ float gelu_f(float v){ return 0.5f * v * (1.f + erff(v * 0.70710678118654752f)); }

// =====================================================================
// K1: conv3x3 stride2 pad1 (64->128ch) + bias + BN(eval) + exact GELU
// block: 256 threads; spatial tile 32x32 (2x2 per thread); 16 oc per block
// grid: (4 spatial tiles, 8 oc groups, 4 batch)
// =====================================================================
__global__ void k_conv(const float* __restrict__ x, const float* __restrict__ w,
                       const float* __restrict__ cb, const float* __restrict__ bng,
                       const float* __restrict__ bnb, const float* __restrict__ bnm,
                       const float* __restrict__ bnv)
{
    __shared__ float in_s[2 * 65 * 65];   // 2 input channels x 65x65 halo tile
    __shared__ float w_s[2 * 9 * 16];     // [ci*9+k][oc] = 288 floats

    const int t  = threadIdx.x;
    const int tx = t & 15, ty = t >> 4;
    const int bx = blockIdx.x;
    const int oh0 = (bx >> 1) * 32, ow0 = (bx & 1) * 32;
    const int oc0 = blockIdx.y * 16;
    const int b   = blockIdx.z;
    const int ih0 = oh0 * 2 - 1, iw0 = ow0 * 2 - 1;

    float acc[2][2][16];
    #pragma unroll
    for (int a = 0; a < 2; a++)
        #pragma unroll
        for (int q = 0; q < 2; q++)
            #pragma unroll
            for (int oc = 0; oc < 16; oc++) acc[a][q][oc] = 0.f;

    for (int cc = 0; cc < CIN; cc += 2) {
        __syncthreads();
        for (int idx = t; idx < 2 * 65 * 65; idx += 256) {
            int ci = idx / 4225, rem = idx - ci * 4225;
            int r = rem / 65, cl = rem - r * 65;
            int ih = ih0 + r, iw = iw0 + cl;
            float v = 0.f;
            if (ih >= 0 && ih < 128 && iw >= 0 && iw < 128)
                v = x[((b * CIN + cc + ci) * 128 + ih) * 128 + iw];
            in_s[idx] = v;
        }
        // FIX: strided loop (288 > blockDim)
        for (int idx = t; idx < 288; idx += 256) {
            int oc = idx & 15, rk = idx >> 4;      // rk = ci*9 + k, 0..17
            int ci = rk / 9, k = rk - ci * 9;
            w_s[idx] = w[(oc0 + oc) * (CIN * 9) + (cc + ci) * 9 + k];
        }
        __syncthreads();

        #pragma unroll
        for (int ci = 0; ci < 2; ci++)
            #pragma unroll
            for (int kh = 0; kh < 3; kh++)
                #pragma unroll
                for (int kw = 0; kw < 3; kw++) {
                    float wr[16];
                    #pragma unroll
                    for (int oc = 0; oc < 16; oc++) wr[oc] = w_s[(ci * 9 + kh * 3 + kw) * 16 + oc];
                    #pragma unroll
                    for (int a = 0; a < 2; a++) {
                        int r = 2 * (ty + a * 16) + kh;
                        #pragma unroll
                        for (int q = 0; q < 2; q++) {
                            int cl = 2 * (tx + q * 16) + kw;
                            float iv = in_s[ci * 4225 + r * 65 + cl];
                            #pragma unroll
                            for (int oc = 0; oc < 16; oc++)
                                acc[a][q][oc] = fmaf(iv, wr[oc], acc[a][q][oc]);
                        }
                    }
                }
    }

    #pragma unroll
    for (int oc = 0; oc < 16; oc++) {
        int c = oc0 + oc;
        float inv = bng[c] * rsqrtf(bnv[c] + 1e-5f);
        float mu = bnm[c], bb = bnb[c], bi = cb[c];
        #pragma unroll
        for (int a = 0; a < 2; a++) {
            int oh = oh0 + ty + a * 16;
            #pragma unroll
            for (int q = 0; q < 2; q++) {
                int ow = ow0 + tx + q * 16;
                float v = acc[a][q][oc] + bi;
                v = (v - mu) * inv + bb;
                g_y[(b * CMOD + c) * L + oh * HW + ow] = gelu_f(v);
            }
        }
    }
}

// =====================================================================
// K2: in-proj GEMM  xz[m][e] = sum_k y[b][k][l] * in_w[e][k]
// =====================================================================
__global__ void k_gemm_xz(const float* __restrict__ in_w)
{
    __shared__ float As[8][128];
    __shared__ float Bs[8][128];
    const int t  = threadIdx.x;
    const int tx = t & 15, ty = t >> 4;
    const int e0 = blockIdx.x * 128;
    const int m0 = blockIdx.y * 128;
    const int b  = m0 >> 12;
    const int l0 = m0 & 4095;

    float acc[8][8];
    #pragma unroll
    for (int i = 0; i < 8; i++)
        #pragma unroll
        for (int j = 0; j < 8; j++) acc[i][j] = 0.f;

    for (int k0 = 0; k0 < CMOD; k0 += 8) {
        __syncthreads();
        {
            int row4 = (t & 31) * 4;
            int k    = t >> 5;
            float4 av = *(const float4*)&g_y[(b * CMOD + k0 + k) * L + l0 + row4];
            *(float4*)&As[k][row4] = av;
            int row = t >> 1, kq = (t & 1) * 4;
            float4 bv = *(const float4*)&in_w[(e0 + row) * CMOD + k0 + kq];
            Bs[kq + 0][row] = bv.x; Bs[kq + 1][row] = bv.y;
            Bs[kq + 2][row] = bv.z; Bs[kq + 3][row] = bv.w;
        }
        __syncthreads();
        #pragma unroll
        for (int k = 0; k < 8; k++) {
            float a[8], bb[8];
            *(float4*)&a[0] = *(float4*)&As[k][ty * 4];
            *(float4*)&a[4] = *(float4*)&As[k][ty * 4 + 64];
            *(float4*)&bb[0] = *(float4*)&Bs[k][tx * 4];
            *(float4*)&bb[4] = *(float4*)&Bs[k][tx * 4 + 64];
            #pragma unroll
            for (int i = 0; i < 8; i++)
                #pragma unroll
                for (int j = 0; j < 8; j++)
                    acc[i][j] = fmaf(a[i], bb[j], acc[i][j]);
        }
    }
    #pragma unroll
    for (int i = 0; i < 8; i++) {
        int m = m0 + ty * 4 + (i & 3) + (i >> 2) * 64;
        float4 v0 = make_float4(acc[i][0], acc[i][1], acc[i][2], acc[i][3]);
        float4 v1 = make_float4(acc[i][4], acc[i][5], acc[i][6], acc[i][7]);
        *(float4*)&g_xz[(size_t)m * 512 + e0 + tx * 4] = v0;
        *(float4*)&g_xz[(size_t)m * 512 + e0 + tx * 4 + 64] = v1;
    }
}

// =====================================================================
// K3: depthwise causal conv1d (k=4, left pad 3) + bias + SiLU
// block: 256 threads (=d), grid (128 l-chunks of 32, 4 b)
// =====================================================================
__global__ void k_conv1d(const float* __restrict__ w, const float* __restrict__ bias)
{
    const int d  = threadIdx.x;
    const int b  = blockIdx.y;
    const int l0 = blockIdx.x * 32;
    const float w0 = w[d * 4 + 0], w1 = w[d * 4 + 1], w2 = w[d * 4 + 2], w3 = w[d * 4 + 3];
    const float bs = bias[d];

    float xm3 = (l0 - 3 >= 0) ? g_xz[(size_t)(b * L + l0 - 3) * 512 + d] : 0.f;
    float xm2 = (l0 - 2 >= 0) ? g_xz[(size_t)(b * L + l0 - 2) * 512 + d] : 0.f;
    float xm1 = (l0 - 1 >= 0) ? g_xz[(size_t)(b * L + l0 - 1) * 512 + d] : 0.f;

    #pragma unroll 4
    for (int l = l0; l < l0 + 32; l++) {
        float xc = g_xz[(size_t)(b * L + l) * 512 + d];
        float v = fmaf(w0, xm3, fmaf(w1, xm2, fmaf(w2, xm1, fmaf(w3, xc, bs))));
        g_xin[(size_t)(b * L + l) * DIN + d] = silu_f(v);
        xm3 = xm2; xm2 = xm1; xm1 = xc;
    }
}

// =====================================================================
// K4: x-proj GEMM  x_dbl[m][e<40] = sum_k x_in[m][k] * xproj_w[e][k]
// weights staged in padded smem (kills uncoalesced global re-reads)
// =====================================================================
__global__ void k_xproj(const float* __restrict__ xpw)
{
    __shared__ float w_s[40 * 260];       // padded rows: stride 260 floats
    __shared__ float xin_s[16 * 256];
    const int m0 = blockIdx.x * 16;
    const int t = threadIdx.y * 40 + threadIdx.x;

    for (int idx = t; idx < 40 * 64; idx += 160) {
        int er = idx >> 6, k4 = idx & 63;
        float4 wv = *(const float4*)&xpw[er * 256 + k4 * 4];
        *(float4*)&w_s[er * 260 + k4 * 4] = wv;
    }
    const float4* src = (const float4*)&g_xin[(size_t)m0 * 256];
    for (int idx = t; idx < 16 * 256 / 4; idx += 160)
        ((float4*)xin_s)[idx] = src[idx];
    __syncthreads();

    const int e = threadIdx.x, ty = threadIdx.y;
    float acc[4] = {0.f, 0.f, 0.f, 0.f};
    #pragma unroll 4
    for (int k4 = 0; k4 < 64; k4++) {
        float4 wv = *(const float4*)&w_s[e * 260 + k4 * 4];
        #pragma unroll
        for (int i = 0; i < 4; i++) {
            float4 a = ((const float4*)xin_s)[(ty * 4 + i) * 64 + k4];
            acc[i] += a.x * wv.x + a.y * wv.y + a.z * wv.z + a.w * wv.w;
        }
    }
    #pragma unroll
    for (int i = 0; i < 4; i++)
        g_xdbl[(size_t)(m0 + ty * 4 + i) * XPROJ_E + e] = acc[i];
}

// =====================================================================
// K5a: scan phase 1 — per-chunk local scan (h from 0), store q and
//      aggregate decay Ap = exp(A * sum(delta))  [exact: prod of exps]
// grid (32 d-groups, NC chunks, 4 b), block 128 (8 d x 16 n)
// =====================================================================
__global__ void k_scan1(const float* __restrict__ A_log, const float* __restrict__ dtw_g,
                        const float* __restrict__ dtb_g)
{
    __shared__ float dt_s [LC * 8];
    __shared__ float B_s  [LC * 16];
    __shared__ float xin_s[LC * 8];
    __shared__ float del_s[LC * 8];

    const int b  = blockIdx.z;
    const int ch = blockIdx.y;
    const int d0 = blockIdx.x * 8;
    const int t  = threadIdx.x;
    const int n  = t & 15, dl = t >> 4;
    const int d  = d0 + dl;
    const float A_dn = -__expf(A_log[d * DST + n]);

    const int dcol = t & 7;
    const int lrow = t >> 3;
    float dtw[8];
    #pragma unroll
    for (int r = 0; r < 8; r++) dtw[r] = dtw_g[(d0 + dcol) * DTR + r];
    const float dtb = dtb_g[d0 + dcol];

    const int mb = b * L + ch * LC;
    #pragma unroll
    for (int j = 0; j < 8; j++) {
        int idx = t + j * 128; int l = idx >> 3, r = idx & 7;
        dt_s[idx] = g_xdbl[(size_t)(mb + l) * XPROJ_E + r];
    }
    #pragma unroll
    for (int j = 0; j < 16; j++) {
        int idx = t + j * 128; int l = idx >> 4, nn = idx & 15;
        B_s[idx] = g_xdbl[(size_t)(mb + l) * XPROJ_E + 8 + nn];
    }
    #pragma unroll
    for (int j = 0; j < 8; j++) {
        int idx = t + j * 128; int l = idx >> 3, dd = idx & 7;
        xin_s[idx] = g_xin[(size_t)(mb + l) * DIN + d0 + dd];
    }
    __syncthreads();
    #pragma unroll
    for (int j = 0; j < 8; j++) {
        int l = lrow + j * 16;
        float v = dtb;
        #pragma unroll
        for (int r = 0; r < 8; r++) v = fmaf(dt_s[l * 8 + r], dtw[r], v);
        del_s[l * 8 + dcol] = softplus_f(v);
    }
    __syncthreads();

    float h = 0.f, sdel = 0.f;
    #pragma unroll 4
    for (int l = 0; l < LC; l++) {
        float dlt = del_s[l * 8 + dl];
        float xv  = xin_s[l * 8 + dl];
        float dA  = __expf(dlt * A_dn);
        h = fmaf(dA, h, dlt * B_s[l * 16 + n] * xv);
        sdel += dlt;
    }
    const int lane = (b * DIN + d) * DST + n;
    g_q [lane * NC + ch] = h;
    g_ap[lane * NC + ch] = __expf(A_dn * sdel);
}

// =====================================================================
// K5b: scan phase 2 — combine chunk aggregates (serial over NC=32)
// =====================================================================
__global__ void k_scan2()
{
    const int lane = blockIdx.x * 128 + threadIdx.x;
    float h = 0.f;
    #pragma unroll
    for (int ch = 0; ch < NC; ch++) {
        g_hin[lane * NC + ch] = h;
        h = fmaf(g_ap[lane * NC + ch], h, g_q[lane * NC + ch]);
    }
}

// =====================================================================
// K5c: scan phase 3 — replay each chunk with known h_in, emit gated y
// =====================================================================
__global__ void k_scan3(const float* __restrict__ A_log, const float* __restrict__ dtw_g,
                        const float* __restrict__ dtb_g, const float* __restrict__ Dp_g)
{
    __shared__ float dt_s [LC * 8];
    __shared__ float B_s  [LC * 16];
    __shared__ float C_s  [LC * 16];
    __shared__ float xin_s[LC * 8];
    __shared__ float del_s[LC * 8];
    __shared__ float ys_s [LC * 8];

    const int b  = blockIdx.z;
    const int ch = blockIdx.y;
    const int d0 = blockIdx.x * 8;
    const int t  = threadIdx.x;
    const int n  = t & 15, dl = t >> 4;
    const int d  = d0 + dl;
    const float A_dn = -__expf(A_log[d * DST + n]);

    const int dcol = t & 7;
    const int lrow = t >> 3;
    float dtw[8];
    #pragma unroll
    for (int r = 0; r < 8; r++) dtw[r] = dtw_g[(d0 + dcol) * DTR + r];
    const float dtb = dtb_g[d0 + dcol];
    const float Dpv = Dp_g[d0 + dcol];

    const int mb = b * L + ch * LC;
    #pragma unroll
    for (int j = 0; j < 8; j++) {
        int idx = t + j * 128; int l = idx >> 3, r = idx & 7;
        dt_s[idx] = g_xdbl[(size_t)(mb + l) * XPROJ_E + r];
    }
    #pragma unroll
    for (int j = 0; j < 16; j++) {
        int idx = t + j * 128; int l = idx >> 4, nn = idx & 15;
        B_s[idx] = g_xdbl[(size_t)(mb + l) * XPROJ_E + 8 + nn];
        C_s[idx] = g_xdbl[(size_t)(mb + l) * XPROJ_E + 24 + nn];
    }
    #pragma unroll
    for (int j = 0; j < 8; j++) {
        int idx = t + j * 128; int l = idx >> 3, dd = idx & 7;
        xin_s[idx] = g_xin[(size_t)(mb + l) * DIN + d0 + dd];
    }
    __syncthreads();
    #pragma unroll
    for (int j = 0; j < 8; j++) {
        int l = lrow + j * 16;
        float v = dtb;
        #pragma unroll
        for (int r = 0; r < 8; r++) v = fmaf(dt_s[l * 8 + r], dtw[r], v);
        del_s[l * 8 + dcol] = softplus_f(v);
    }
    __syncthreads();

    const int lane = (b * DIN + d) * DST + n;
    float h = g_hin[lane * NC + ch];
    #pragma unroll 4
    for (int l = 0; l < LC; l++) {
        float dlt = del_s[l * 8 + dl];
        float xv  = xin_s[l * 8 + dl];
        float dA  = __expf(dlt * A_dn);
        h = fmaf(dA, h, dlt * B_s[l * 16 + n] * xv);
        float p = h * C_s[l * 16 + n];
        p += __shfl_xor_sync(0xffffffffu, p, 8);
        p += __shfl_xor_sync(0xffffffffu, p, 4);
        p += __shfl_xor_sync(0xffffffffu, p, 2);
        p += __shfl_xor_sync(0xffffffffu, p, 1);
        if (n == 0) ys_s[l * 8 + dl] = p;
    }
    __syncthreads();
    #pragma unroll
    for (int j = 0; j < 8; j++) {
        int idx = t + j * 128; int l = idx >> 3, dd = idx & 7;
        float z = g_xz[(size_t)(mb + l) * 512 + 256 + d0 + dd];
        float yv = fmaf(xin_s[idx], Dpv, ys_s[idx]) * silu_f(z);
        g_yg[(size_t)(mb + l) * DIN + d0 + dd] = yv;
    }
}

// =====================================================================
// K6: out-proj GEMM + residual
// =====================================================================
__global__ void k_gemm_out(const float* __restrict__ ow, float* __restrict__ out)
{
    __shared__ float As[8][128];
    __shared__ float Bs[8][128];
    const int t  = threadIdx.x;
    const int tx = t & 15, ty = t >> 4;
    const int m0 = blockIdx.x * 128;
    const int b  = m0 >> 12;
    const int l0 = m0 & 4095;

    float acc[8][8];
    #pragma unroll
    for (int i = 0; i < 8; i++)
        #pragma unroll
        for (int j = 0; j < 8; j++) acc[i][j] = 0.f;

    for (int k0 = 0; k0 < DIN; k0 += 8) {
        __syncthreads();
        {
            int row = t >> 1, kq = (t & 1) * 4;
            float4 av = *(const float4*)&g_yg[(size_t)(m0 + row) * DIN + k0 + kq];
            As[kq + 0][row] = av.x; As[kq + 1][row] = av.y;
            As[kq + 2][row] = av.z; As[kq + 3][row] = av.w;
            float4 bv = *(const float4*)&ow[row * DIN + k0 + kq];
            Bs[kq + 0][row] = bv.x; Bs[kq + 1][row] = bv.y;
            Bs[kq + 2][row] = bv.z; Bs[kq + 3][row] = bv.w;
        }
        __syncthreads();
        #pragma unroll
        for (int k = 0; k < 8; k++) {
            float am[8], bc[8];
            *(float4*)&am[0] = *(float4*)&As[k][tx * 4];
            *(float4*)&am[4] = *(float4*)&As[k][tx * 4 + 64];
            *(float4*)&bc[0] = *(float4*)&Bs[k][ty * 4];
            *(float4*)&bc[4] = *(float4*)&Bs[k][ty * 4 + 64];
            #pragma unroll
            for (int ci = 0; ci < 8; ci++)
                #pragma unroll
                for (int mj = 0; mj < 8; mj++)
                    acc[ci][mj] = fmaf(bc[ci], am[mj], acc[ci][mj]);
        }
    }
    #pragma unroll
    for (int ci = 0; ci < 8; ci++) {
        int c = ty * 4 + (ci & 3) + (ci >> 2) * 64;
        size_t base = (size_t)(b * CMOD + c) * L + l0;
        float4 r0 = *(const float4*)&g_y[base + tx * 4];
        r0.x += acc[ci][0]; r0.y += acc[ci][1]; r0.z += acc[ci][2]; r0.w += acc[ci][3];
        *(float4*)&out[base + tx * 4] = r0;
        float4 r1 = *(const float4*)&g_y[base + tx * 4 + 64];
        r1.x += acc[ci][4]; r1.y += acc[ci][5]; r1.z += acc[ci][6]; r1.w += acc[ci][7];
        *(float4*)&out[base + tx * 4 + 64] = r1;
    }
}

// =====================================================================
extern "C" void kernel_launch(void* const* d_in, const int* in_sizes, int n_in,
                              void* d_out, int out_size)
{
    const float* x        = (const float*)d_in[0];
    const float* conv_w   = (const float*)d_in[1];
    const float* conv_b   = (const float*)d_in[2];
    const float* bn_g     = (const float*)d_in[3];
    const float* bn_b     = (const float*)d_in[4];
    const float* bn_mean  = (const float*)d_in[5];
    const float* bn_var   = (const float*)d_in[6];
    const float* in_w     = (const float*)d_in[7];
    const float* conv1d_w = (const float*)d_in[8];
    const float* conv1d_b = (const float*)d_in[9];
    const float* xproj_w  = (const float*)d_in[10];
    const float* dtproj_w = (const float*)d_in[11];
    const float* dtproj_b = (const float*)d_in[12];
    const float* A_log    = (const float*)d_in[13];
    const float* Dp       = (const float*)d_in[14];
    const float* out_w    = (const float*)d_in[15];
    float* out = (float*)d_out;

    k_conv    <<<dim3(4, 8, 4), 256>>>(x, conv_w, conv_b, bn_g, bn_b, bn_mean, bn_var);
    k_gemm_xz <<<dim3(4, 128), 256>>>(in_w);
    k_conv1d  <<<dim3(128, 4), 256>>>(conv1d_w, conv1d_b);
    k_xproj   <<<1024, dim3(40, 4)>>>(xproj_w);
    k_scan1   <<<dim3(32, NC, 4), 128>>>(A_log, dtproj_w, dtproj_b);
    k_scan2   <<<128, 128>>>();
    k_scan3   <<<dim3(32, NC, 4), 128>>>(A_log, dtproj_w, dtproj_b, Dp);
    k_gemm_out<<<128, 256>>>(out_w, out);
}